// round 13
// baseline (speedup 1.0000x reference)
#include <cuda_runtime.h>
#include <cuda_fp16.h>
#include <cuda_bf16.h>

// Problem constants
#define Bn   64
#define Tn   128
#define Fn   128
#define Hn   128
#define LATn 512
#define UNF  6
#define PADW 132   // fp32 padded row stride (words)
#define PADH 68    // half2-pair padded row stride (u32 words)

// ---------------------------------------------------------------------------
// Device scratch (no allocations allowed)
// ---------------------------------------------------------------------------
__device__ float2 g_ND0[Tn * Bn * Hn];         // layer-0 sensory (num,den)
__device__ float2 g_ND1[Tn * Bn * Hn];         // layer-1 sensory (num,den)
__device__ float  g_h1[Tn * Bn * Hn];          // layer-1 hidden seq (final)
__device__ float  g_part[32 * 2 * Bn * LATn];  // head GEMM k-split partials
__device__ int    g_prog[Bn];                  // per-batch pipeline progress

// ---------------------------------------------------------------------------
// helpers
// ---------------------------------------------------------------------------
__device__ __forceinline__ int ld_acq(const int* p) {
    int v;
    asm volatile("ld.global.acquire.gpu.b32 %0, [%1];" : "=r"(v) : "l"(p) : "memory");
    return v;
}
__device__ __forceinline__ void st_rel(int* p, int v) {
    asm volatile("st.global.release.gpu.b32 [%0], %1;" :: "l"(p), "r"(v) : "memory");
}

__global__ void init_kernel(int* prog) { prog[threadIdx.x] = 0; }

// ---------------------------------------------------------------------------
// Layer-0 sensory precompute (full fp32). grid 512 x 256 threads.
// ---------------------------------------------------------------------------
__global__ __launch_bounds__(256, 1)
void sensory_kernel(const float* __restrict__ U, int stride_t, int stride_b,
                    const float* __restrict__ ssig, const float* __restrict__ smu,
                    const float* __restrict__ sw,   const float* __restrict__ sev,
                    float2* __restrict__ ND)
{
    extern __shared__ float sm[];
    float* sHs = sm;                      // [128][PADW]
    float* sNh = sm + 128 * PADW;         // [128][PADW]
    float* sCc = sm + 2 * 128 * PADW;     // [128][PADW]
    float* su  = sm + 3 * 128 * PADW;     // [16][128]

    const int tid   = threadIdx.x;
    const int j     = tid & 127;
    const int half  = tid >> 7;
    const int pair0 = blockIdx.x * 16;

    for (int idx = tid; idx < Hn * Hn; idx += 256) {
        int i  = idx >> 7;
        int jj = idx & 127;
        float sg = ssig[idx];
        float m  = smu[idx];
        sHs[jj * PADW + i] = 0.5f * sg;
        sNh[jj * PADW + i] = -0.5f * sg * m;
        sCc[jj * PADW + i] = 0.5f * sw[idx] * sev[idx];
    }
    for (int idx = tid; idx < 16 * Hn; idx += 256) {
        int p  = idx >> 7;
        int i  = idx & 127;
        int pr = pair0 + p;
        int t  = pr >> 6;
        int b  = pr & 63;
        su[idx] = U[t * stride_t + b * stride_b + i];
    }
    __syncthreads();

    float cC = 0.f, cA = 0.f;
    {
        const float4* cr = (const float4*)(sCc + j * PADW);
        #pragma unroll 8
        for (int q = 0; q < 32; ++q) {
            float4 c4 = cr[q];
            cC += c4.x + c4.y + c4.z + c4.w;
            cA += fabsf(c4.x) + fabsf(c4.y) + fabsf(c4.z) + fabsf(c4.w);
        }
    }

    const float4* hsr = (const float4*)(sHs + j * PADW);
    const float4* nhr = (const float4*)(sNh + j * PADW);
    const float4* ccr = (const float4*)(sCc + j * PADW);

    for (int pg2 = 0; pg2 < 2; ++pg2) {
        const int pg = half * 2 + pg2;
        const float4* u0r = (const float4*)(su + (pg * 4 + 0) * Hn);
        const float4* u1r = (const float4*)(su + (pg * 4 + 1) * Hn);
        const float4* u2r = (const float4*)(su + (pg * 4 + 2) * Hn);
        const float4* u3r = (const float4*)(su + (pg * 4 + 3) * Hn);
        float n0 = cC, n1 = cC, n2 = cC, n3 = cC;
        float d0 = cA, d1 = cA, d2 = cA, d3 = cA;
        #pragma unroll 4
        for (int q = 0; q < 32; ++q) {
            float4 hs = hsr[q], nh = nhr[q], cc = ccr[q];
            float4 u0 = u0r[q], u1 = u1r[q], u2 = u2r[q], u3 = u3r[q];
            #pragma unroll
            for (int e = 0; e < 4; ++e) {
                float hse = (&hs.x)[e];
                float nhe = (&nh.x)[e];
                float c   = (&cc.x)[e];
                float ac  = fabsf(c);
                float t0, t1, t2, t3;
                float a0 = fmaf((&u0.x)[e], hse, nhe);
                float a1 = fmaf((&u1.x)[e], hse, nhe);
                float a2 = fmaf((&u2.x)[e], hse, nhe);
                float a3 = fmaf((&u3.x)[e], hse, nhe);
                asm("tanh.approx.f32 %0, %1;" : "=f"(t0) : "f"(a0));
                asm("tanh.approx.f32 %0, %1;" : "=f"(t1) : "f"(a1));
                asm("tanh.approx.f32 %0, %1;" : "=f"(t2) : "f"(a2));
                asm("tanh.approx.f32 %0, %1;" : "=f"(t3) : "f"(a3));
                n0 = fmaf(c, t0, n0);  d0 = fmaf(ac, t0, d0);
                n1 = fmaf(c, t1, n1);  d1 = fmaf(ac, t1, d1);
                n2 = fmaf(c, t2, n2);  d2 = fmaf(ac, t2, d2);
                n3 = fmaf(c, t3, n3);  d3 = fmaf(ac, t3, d3);
            }
        }
        int o = (pair0 + pg * 4) * Hn + j;
        ND[o]          = make_float2(n0, d0);
        ND[o + Hn]     = make_float2(n1, d1);
        ND[o + 2 * Hn] = make_float2(n2, d2);
        ND[o + 3 * Hn] = make_float2(n3, d3);
    }
}

// ---------------------------------------------------------------------------
// Pipelined dual-layer LTC, full fp32 datapath (round-5 numerics).
// grid = 128: block < 64 -> layer 0 batch b, else layer 1 batch b.
// 512 threads: j = tid&127, k = tid>>7; thread covers i in [32k,32k+32).
//
// ONE barrier per unfold: all threads compute partials (v via __shfl_sync:
// warp k's lanes hold exactly v[32k..32k+32)), store float2 partials
// (double-buffered by parity), barrier, then EVERY thread redundantly
// reduces + divides -> v_p stays in registers. No sv array, no writer
// serialization.
// Layer-0 blocks compute layer-1's sensory ND1 inline (half2 params, fp32
// math) and release a per-batch progress flag.
// ---------------------------------------------------------------------------
__global__ __launch_bounds__(512, 1)
void pipe_kernel(const float* __restrict__ sigma, const float* __restrict__ mu,
                 const float* __restrict__ w,     const float* __restrict__ erev,
                 const float* __restrict__ gleak, const float* __restrict__ vleak,
                 const float* __restrict__ cmv,
                 const float* __restrict__ s_sig, const float* __restrict__ s_mu,
                 const float* __restrict__ s_w,   const float* __restrict__ s_ev,
                 const float2* __restrict__ ND0,  float2* __restrict__ ND1,
                 float* __restrict__ h1,          int* __restrict__ prog)
{
    extern __shared__ float sm[];
    float*    sC    = sm;                            // [128][PADW] fp32 C
    unsigned* sHs2  = (unsigned*)(sm + 128 * PADW);  // [128][PADH] half2 (hs pairs)
    unsigned* sNh2  = sHs2 + 128 * PADH;             // half2 (nh pairs)
    unsigned* sCs2  = sNh2 + 128 * PADH;             // half2 (c pairs)
    float2*   redND = (float2*)(sCs2 + 128 * PADH);  // 2 x 512 float2
    float2*   senND = redND + 1024;                  // 512 float2

    const int layer = blockIdx.x >> 6;
    const int b     = blockIdx.x & 63;
    const int tid   = threadIdx.x;
    const int j     = tid & 127;
    const int k     = tid >> 7;
    const int lane  = tid & 31;
    const int p     = k * 32 + lane;
    const bool wrt  = ((tid >> 5) & 3) == 0;   // warps 0,4,8,12 (j-group 0)
    const int lofsM = layer * Hn * Hn;
    const int lofsV = layer * Hn;

    // ---- stage recurrent params: hs/nh fp32 regs, C fp32 in SMEM [j][i]
    float hsig[32], nhm[32];
    {
        float cpart = 0.f, apart = 0.f;
        #pragma unroll
        for (int s = 0; s < 32; ++s) {
            int i   = k * 32 + s;
            int idx = lofsM + i * Hn + j;
            float sg = sigma[idx];
            float m  = mu[idx];
            hsig[s] = 0.5f * sg;
            nhm[s]  = -0.5f * sg * m;
            float c = 0.5f * w[idx] * erev[idx];
            sC[j * PADW + i] = c;
            cpart += c;
            apart += fabsf(c);
        }
        redND[k * 128 + j] = make_float2(cpart, apart);
    }

    // ---- layer-0: stage layer-1 sensory params (pair-packed half2)
    if (layer == 0) {
        float csum = 0.f, asum = 0.f;
        #pragma unroll
        for (int s = 0; s < 16; ++s) {
            int i0   = k * 32 + 2 * s;
            int idx0 = i0 * Hn + j;
            int idx1 = idx0 + Hn;
            float sg0 = s_sig[idx0], sg1 = s_sig[idx1];
            float m0  = s_mu[idx0],  m1  = s_mu[idx1];
            __half2 h2 = __floats2half2_rn(0.5f * sg0, 0.5f * sg1);
            __half2 n2 = __floats2half2_rn(-0.5f * sg0 * m0, -0.5f * sg1 * m1);
            sHs2[j * PADH + 16 * k + s] = *reinterpret_cast<unsigned*>(&h2);
            sNh2[j * PADH + 16 * k + s] = *reinterpret_cast<unsigned*>(&n2);
            float c0 = 0.5f * s_w[idx0] * s_ev[idx0];
            float c1 = 0.5f * s_w[idx1] * s_ev[idx1];
            __half2 c2 = __floats2half2_rn(c0, c1);
            sCs2[j * PADH + 16 * k + s] = *reinterpret_cast<unsigned*>(&c2);
            csum += c0 + c1;
            asum += fabsf(c0) + fabsf(c1);
        }
        senND[k * 128 + j] = make_float2(csum, asum);
    }
    __syncthreads();

    // per-p constants (fp32, exact) -- every thread for its p
    float2 c0r = redND[p], c1r = redND[128 + p], c2r = redND[256 + p], c3r = redND[384 + p];
    float cC = c0r.x + c1r.x + c2r.x + c3r.x;
    float cA = c0r.y + c1r.y + c2r.y + c3r.y;
    const float gl    = gleak[lofsV + p];
    const float cmt   = cmv[lofsV + p] * (float)UNF;
    const float baseN = gl * vleak[lofsV + p] + cC;
    const float baseD = cmt + gl + cA + 1e-8f;
    float csN = 0.f, csA = 0.f;
    if (layer == 0) {
        float2 s0 = senND[p], s1 = senND[128 + p], s2 = senND[256 + p], s3 = senND[384 + p];
        csN = s0.x + s1.x + s2.x + s3.x;
        csA = s0.y + s1.y + s2.y + s3.y;
    }
    __syncthreads();

    const float4* crow = (const float4*)(sC + j * PADW + 32 * k);    // 8 float4
    const uint4*  hrow = (const uint4*)(sHs2 + j * PADH) + 4 * k;    // 4 x (4 half2)
    const uint4*  nrow = (const uint4*)(sNh2 + j * PADH) + 4 * k;
    const uint4*  srow = (const uint4*)(sCs2 + j * PADH) + 4 * k;

    float vreg = 0.f;   // ALL threads: fp32 recurrent state v_p (redundant x4)

    for (int t = 0; t < Tn; ++t) {
        const int o = (t * Bn + b) * Hn;
        float ns, ds;
        if (layer == 0) {
            float2 nd = ND0[o + p];   // k-groups hit same lines -> L1
            ns = nd.x; ds = nd.y;
        } else {
            if (tid == 0) {
                while (ld_acq(&prog[b]) < t + 1) __nanosleep(64);
            }
            __syncthreads();
            float2 nd = __ldcg(ND1 + o + p);
            ns = nd.x; ds = nd.y;
        }

        #pragma unroll 1
        for (int u = 0; u < UNF; ++u) {
            const int par = u & 1;
            float num = 0.f, den = 0.f;
            #pragma unroll
            for (int s4 = 0; s4 < 8; ++s4) {
                float4 c4 = crow[s4];
                #pragma unroll
                for (int e = 0; e < 4; ++e) {
                    int s = s4 * 4 + e;
                    float vs = __shfl_sync(0xffffffffu, vreg, s);
                    float arg = fmaf(vs, hsig[s], nhm[s]);
                    float th;
                    asm("tanh.approx.f32 %0, %1;" : "=f"(th) : "f"(arg));
                    float c = (&c4.x)[e];
                    num = fmaf(c, th, num);
                    den = fmaf(fabsf(c), th, den);
                }
            }
            redND[par * 512 + k * 128 + j] = make_float2(num, den);
            __syncthreads();
            // every thread redundantly computes v_p (no writer serialization)
            const float2* rp = redND + par * 512;
            float2 r0 = rp[p], r1 = rp[128 + p], r2 = rp[256 + p], r3 = rp[384 + p];
            float rn = r0.x + r1.x + r2.x + r3.x;
            float rd = r0.y + r1.y + r2.y + r3.y;
            float tn = rn + ns + baseN + cmt * vreg;
            float td = rd + ds + baseD;
            vreg = __fdividef(tn, td);
        }

        if (layer == 0) {
            // inline sensory pass for layer 1 (half2 params -> fp32 math)
            float nsum = 0.f, dsum = 0.f;
            #pragma unroll
            for (int g = 0; g < 4; ++g) {
                uint4 h4 = hrow[g];
                uint4 n4 = nrow[g];
                uint4 c4 = srow[g];
                const __half2* hh = reinterpret_cast<const __half2*>(&h4);
                const __half2* nn = reinterpret_cast<const __half2*>(&n4);
                const __half2* cc = reinterpret_cast<const __half2*>(&c4);
                #pragma unroll
                for (int e = 0; e < 4; ++e) {
                    int s = g * 8 + e * 2;
                    float v0 = __shfl_sync(0xffffffffu, vreg, s);
                    float v1 = __shfl_sync(0xffffffffu, vreg, s + 1);
                    float2 a = __half22float2(hh[e]);
                    float2 m = __half22float2(nn[e]);
                    float2 c = __half22float2(cc[e]);
                    float g0 = fmaf(v0, a.x, m.x);
                    float g1 = fmaf(v1, a.y, m.y);
                    float th0, th1;
                    asm("tanh.approx.f32 %0, %1;" : "=f"(th0) : "f"(g0));
                    asm("tanh.approx.f32 %0, %1;" : "=f"(th1) : "f"(g1));
                    nsum = fmaf(c.x, th0, nsum);
                    dsum = fmaf(fabsf(c.x), th0, dsum);
                    nsum = fmaf(c.y, th1, nsum);
                    dsum = fmaf(fabsf(c.y), th1, dsum);
                }
            }
            senND[k * 128 + j] = make_float2(nsum, dsum);
            __syncthreads();
            if (wrt) {
                float2 s0 = senND[p], s1 = senND[128 + p], s2 = senND[256 + p], s3 = senND[384 + p];
                float nn = s0.x + s1.x + s2.x + s3.x + csN;
                float dd = s0.y + s1.y + s2.y + s3.y + csA;
                ND1[o + p] = make_float2(nn, dd);
            }
            __threadfence();
            __syncthreads();
            if (tid == 0) st_rel(&prog[b], t + 1);
        } else {
            if (wrt) h1[o + p] = vreg;
        }
    }
}

// ---------------------------------------------------------------------------
// Head GEMM: out_part = h[64,16384] @ W^T (W = [512,16384]), k-split by 32.
// ---------------------------------------------------------------------------
__global__ __launch_bounds__(128)
void heads_kernel(const float* __restrict__ hseq,
                  const float* __restrict__ Wm, const float* __restrict__ Wl,
                  float* __restrict__ part)
{
    extern __shared__ float sm[];
    float* a_s = sm;               // [128][66] transposed h tile
    float* w_s = sm + 128 * 66;    // [32][128]

    const int tid  = threadIdx.x;
    const int lt   = blockIdx.x;
    const int head = blockIdx.y;
    const int ks   = blockIdx.z;
    const float* W = head ? Wl : Wm;
    const int lat0 = lt * 32;
    const int bg   = tid & 15;
    const int lg   = tid >> 4;

    float acc[4][4];
    #pragma unroll
    for (int a = 0; a < 4; ++a)
        #pragma unroll
        for (int c = 0; c < 4; ++c) acc[a][c] = 0.f;

    for (int t = ks * 4; t < ks * 4 + 4; ++t) {
        __syncthreads();
        const float* src = hseq + t * Bn * Hn;
        #pragma unroll
        for (int r = 0; r < 64; ++r) {
            int idx = r * 128 + tid;
            a_s[(idx & 127) * 66 + (idx >> 7)] = src[idx];
        }
        #pragma unroll
        for (int r = 0; r < 32; ++r)
            w_s[r * 128 + tid] = W[(lat0 + r) * (Tn * Hn) + t * Hn + tid];
        __syncthreads();

        #pragma unroll 4
        for (int jj = 0; jj < 128; ++jj) {
            float2 a01 = *reinterpret_cast<const float2*>(&a_s[jj * 66 + bg * 4]);
            float2 a23 = *reinterpret_cast<const float2*>(&a_s[jj * 66 + bg * 4 + 2]);
            float av[4] = {a01.x, a01.y, a23.x, a23.y};
            float w0 = w_s[(lg * 4 + 0) * 128 + jj];
            float w1 = w_s[(lg * 4 + 1) * 128 + jj];
            float w2 = w_s[(lg * 4 + 2) * 128 + jj];
            float w3 = w_s[(lg * 4 + 3) * 128 + jj];
            #pragma unroll
            for (int bi = 0; bi < 4; ++bi) {
                acc[bi][0] = fmaf(av[bi], w0, acc[bi][0]);
                acc[bi][1] = fmaf(av[bi], w1, acc[bi][1]);
                acc[bi][2] = fmaf(av[bi], w2, acc[bi][2]);
                acc[bi][3] = fmaf(av[bi], w3, acc[bi][3]);
            }
        }
    }
    #pragma unroll
    for (int bi = 0; bi < 4; ++bi)
        #pragma unroll
        for (int li = 0; li < 4; ++li)
            part[(((ks * 2 + head) * Bn) + bg * 4 + bi) * LATn + lat0 + lg * 4 + li]
                = acc[bi][li];
}

// ---------------------------------------------------------------------------
// Epilogue: sum k-split partials, add bias, exp for sigma head.
// ---------------------------------------------------------------------------
__global__ __launch_bounds__(256)
void epilogue_kernel(const float* __restrict__ part,
                     const float* __restrict__ mu_b, const float* __restrict__ ls_b,
                     float* __restrict__ out)
{
    int idx  = blockIdx.x * 256 + threadIdx.x;
    int head = idx >> 15;
    int r    = idx & 32767;
    int lat  = r & 511;
    float s = 0.f;
    #pragma unroll
    for (int ks = 0; ks < 32; ++ks)
        s += part[(ks * 2 + head) * Bn * LATn + r];
    s += head ? ls_b[lat] : mu_b[lat];
    out[idx] = head ? expf(s) : s;
}

// ---------------------------------------------------------------------------
// Launch
// ---------------------------------------------------------------------------
extern "C" void kernel_launch(void* const* d_in, const int* in_sizes, int n_in,
                              void* d_out, int out_size)
{
    const float* x      = (const float*)d_in[0];
    const float* gleak  = (const float*)d_in[1];
    const float* vleak  = (const float*)d_in[2];
    const float* cmv    = (const float*)d_in[3];
    const float* sigma  = (const float*)d_in[4];
    const float* mu_syn = (const float*)d_in[5];
    const float* w      = (const float*)d_in[6];
    const float* erev   = (const float*)d_in[7];
    const float* s_sig  = (const float*)d_in[8];
    const float* s_mu   = (const float*)d_in[9];
    const float* s_w    = (const float*)d_in[10];
    const float* s_ev   = (const float*)d_in[11];
    const float* mu_w   = (const float*)d_in[12];
    const float* mu_b   = (const float*)d_in[13];
    const float* ls_w   = (const float*)d_in[14];
    const float* ls_b   = (const float*)d_in[15];
    float* out = (float*)d_out;

    float2 *ND0, *ND1;
    float *h1, *part;
    int* prog;
    cudaGetSymbolAddress((void**)&ND0,  g_ND0);
    cudaGetSymbolAddress((void**)&ND1,  g_ND1);
    cudaGetSymbolAddress((void**)&h1,   g_h1);
    cudaGetSymbolAddress((void**)&part, g_part);
    cudaGetSymbolAddress((void**)&prog, g_prog);

    const int SENS_SMEM = (3 * 128 * PADW + 16 * Hn) * 4;            // 210944 B
    // pipe smem words: C 128*PADW=16896, sensory params 3*128*PADH=26112,
    // redND 2*512 float2 = 2048, senND 512 float2 = 1024  -> 46080 words
    const int PIPE_SMEM = (128 * PADW + 3 * 128 * PADH + 2048 + 1024) * 4;  // 184320 B
    const int GEMM_SMEM = (128 * 66 + 32 * 128) * 4;                 // 50176 B
    cudaFuncSetAttribute(sensory_kernel, cudaFuncAttributeMaxDynamicSharedMemorySize, SENS_SMEM);
    cudaFuncSetAttribute(pipe_kernel,    cudaFuncAttributeMaxDynamicSharedMemorySize, PIPE_SMEM);
    cudaFuncSetAttribute(heads_kernel,   cudaFuncAttributeMaxDynamicSharedMemorySize, GEMM_SMEM);

    init_kernel<<<1, Bn>>>(prog);
    // layer-0 sensory from x [B,T,F]: u[t][b][i] -> stride_t=F, stride_b=T*F
    sensory_kernel<<<512, 256, SENS_SMEM>>>(x, Fn, Tn * Fn,
                                            s_sig, s_mu, s_w, s_ev, ND0);
    // pipelined dual-layer recurrence (layer-1 sensory params offset by H*H)
    pipe_kernel<<<128, 512, PIPE_SMEM>>>(sigma, mu_syn, w, erev, gleak, vleak, cmv,
                                         s_sig + Hn * Hn, s_mu + Hn * Hn,
                                         s_w + Hn * Hn, s_ev + Hn * Hn,
                                         ND0, ND1, h1, prog);
    // heads
    heads_kernel<<<dim3(16, 2, 32), 128, GEMM_SMEM>>>(h1, mu_w, ls_w, part);
    epilogue_kernel<<<(2 * Bn * LATn) / 256, 256>>>(part, mu_b, ls_b, out);
}

// round 15
// speedup vs baseline: 1.0388x; 1.0388x over previous
#include <cuda_runtime.h>
#include <cuda_fp16.h>
#include <cuda_bf16.h>

// Problem constants
#define Bn   64
#define Tn   128
#define Fn   128
#define Hn   128
#define LATn 512
#define UNF  6
#define PADW 132   // fp32 padded row stride (words)
#define PADH 68    // half2-pair padded row stride (u32 words)

// ---------------------------------------------------------------------------
// Device scratch (no allocations allowed)
// ---------------------------------------------------------------------------
__device__ float2 g_ND0[Tn * Bn * Hn];         // layer-0 sensory (num,den)
__device__ float2 g_ND1[Tn * Bn * Hn];         // layer-1 sensory PARTIAL (producer half)
__device__ float  g_v1[Tn * Bn * Hn];          // layer-0 hidden v(t) handoff
__device__ float  g_h1[Tn * Bn * Hn];          // layer-1 hidden seq (final)
__device__ float  g_part[32 * 2 * Bn * LATn];  // head GEMM k-split partials
__device__ int    g_prog[Bn];                  // per-batch pipeline progress

// ---------------------------------------------------------------------------
// helpers
// ---------------------------------------------------------------------------
__device__ __forceinline__ int ld_acq(const int* p) {
    int v;
    asm volatile("ld.global.acquire.gpu.b32 %0, [%1];" : "=r"(v) : "l"(p) : "memory");
    return v;
}
__device__ __forceinline__ void st_rel(int* p, int v) {
    asm volatile("st.global.release.gpu.b32 [%0], %1;" :: "l"(p), "r"(v) : "memory");
}

__global__ void init_kernel(int* prog) { prog[threadIdx.x] = 0; }

// ---------------------------------------------------------------------------
// Layer-0 sensory precompute (full fp32). grid 512 x 256 threads.
// ---------------------------------------------------------------------------
__global__ __launch_bounds__(256, 1)
void sensory_kernel(const float* __restrict__ U, int stride_t, int stride_b,
                    const float* __restrict__ ssig, const float* __restrict__ smu,
                    const float* __restrict__ sw,   const float* __restrict__ sev,
                    float2* __restrict__ ND)
{
    extern __shared__ float sm[];
    float* sHs = sm;                      // [128][PADW]
    float* sNh = sm + 128 * PADW;         // [128][PADW]
    float* sCc = sm + 2 * 128 * PADW;     // [128][PADW]
    float* su  = sm + 3 * 128 * PADW;     // [16][128]

    const int tid   = threadIdx.x;
    const int j     = tid & 127;
    const int half  = tid >> 7;
    const int pair0 = blockIdx.x * 16;

    for (int idx = tid; idx < Hn * Hn; idx += 256) {
        int i  = idx >> 7;
        int jj = idx & 127;
        float sg = ssig[idx];
        float m  = smu[idx];
        sHs[jj * PADW + i] = 0.5f * sg;
        sNh[jj * PADW + i] = -0.5f * sg * m;
        sCc[jj * PADW + i] = 0.5f * sw[idx] * sev[idx];
    }
    for (int idx = tid; idx < 16 * Hn; idx += 256) {
        int p  = idx >> 7;
        int i  = idx & 127;
        int pr = pair0 + p;
        int t  = pr >> 6;
        int b  = pr & 63;
        su[idx] = U[t * stride_t + b * stride_b + i];
    }
    __syncthreads();

    float cC = 0.f, cA = 0.f;
    {
        const float4* cr = (const float4*)(sCc + j * PADW);
        #pragma unroll 8
        for (int q = 0; q < 32; ++q) {
            float4 c4 = cr[q];
            cC += c4.x + c4.y + c4.z + c4.w;
            cA += fabsf(c4.x) + fabsf(c4.y) + fabsf(c4.z) + fabsf(c4.w);
        }
    }

    const float4* hsr = (const float4*)(sHs + j * PADW);
    const float4* nhr = (const float4*)(sNh + j * PADW);
    const float4* ccr = (const float4*)(sCc + j * PADW);

    for (int pg2 = 0; pg2 < 2; ++pg2) {
        const int pg = half * 2 + pg2;
        const float4* u0r = (const float4*)(su + (pg * 4 + 0) * Hn);
        const float4* u1r = (const float4*)(su + (pg * 4 + 1) * Hn);
        const float4* u2r = (const float4*)(su + (pg * 4 + 2) * Hn);
        const float4* u3r = (const float4*)(su + (pg * 4 + 3) * Hn);
        float n0 = cC, n1 = cC, n2 = cC, n3 = cC;
        float d0 = cA, d1 = cA, d2 = cA, d3 = cA;
        #pragma unroll 4
        for (int q = 0; q < 32; ++q) {
            float4 hs = hsr[q], nh = nhr[q], cc = ccr[q];
            float4 u0 = u0r[q], u1 = u1r[q], u2 = u2r[q], u3 = u3r[q];
            #pragma unroll
            for (int e = 0; e < 4; ++e) {
                float hse = (&hs.x)[e];
                float nhe = (&nh.x)[e];
                float c   = (&cc.x)[e];
                float ac  = fabsf(c);
                float t0, t1, t2, t3;
                float a0 = fmaf((&u0.x)[e], hse, nhe);
                float a1 = fmaf((&u1.x)[e], hse, nhe);
                float a2 = fmaf((&u2.x)[e], hse, nhe);
                float a3 = fmaf((&u3.x)[e], hse, nhe);
                asm("tanh.approx.f32 %0, %1;" : "=f"(t0) : "f"(a0));
                asm("tanh.approx.f32 %0, %1;" : "=f"(t1) : "f"(a1));
                asm("tanh.approx.f32 %0, %1;" : "=f"(t2) : "f"(a2));
                asm("tanh.approx.f32 %0, %1;" : "=f"(t3) : "f"(a3));
                n0 = fmaf(c, t0, n0);  d0 = fmaf(ac, t0, d0);
                n1 = fmaf(c, t1, n1);  d1 = fmaf(ac, t1, d1);
                n2 = fmaf(c, t2, n2);  d2 = fmaf(ac, t2, d2);
                n3 = fmaf(c, t3, n3);  d3 = fmaf(ac, t3, d3);
            }
        }
        int o = (pair0 + pg * 4) * Hn + j;
        ND[o]          = make_float2(n0, d0);
        ND[o + Hn]     = make_float2(n1, d1);
        ND[o + 2 * Hn] = make_float2(n2, d2);
        ND[o + 3 * Hn] = make_float2(n3, d3);
    }
}

// ---------------------------------------------------------------------------
// Pipelined dual-layer LTC, full fp32 datapath, BALANCED 6.5 units/side.
// grid = 128: block < 64 -> layer 0 batch b, else layer 1 batch b.
// 512 threads: j = tid&127, k = tid>>7; thread covers i in [32k,32k+32).
//
// Producer (layer 0): 6 unfolds + HALF the layer-1 sensory (i in
// [32k,32k+16) per thread), ships partial ND1 + v(t), releases flag
// (cumulative st.release.gpu after __syncthreads -- no threadfence).
// Consumer (layer 1): acquires, loads v(t), computes the OTHER sensory
// half (i in [32k+16,32k+32)), sums with producer partial, runs 6 unfolds.
// ---------------------------------------------------------------------------
__global__ __launch_bounds__(512, 1)
void pipe_kernel(const float* __restrict__ sigma, const float* __restrict__ mu,
                 const float* __restrict__ w,     const float* __restrict__ erev,
                 const float* __restrict__ gleak, const float* __restrict__ vleak,
                 const float* __restrict__ cmv,
                 const float* __restrict__ s_sig, const float* __restrict__ s_mu,
                 const float* __restrict__ s_w,   const float* __restrict__ s_ev,
                 const float2* __restrict__ ND0,  float2* __restrict__ ND1,
                 float* __restrict__ v1,          float* __restrict__ h1,
                 int* __restrict__ prog)
{
    extern __shared__ float sm[];
    float*    sC    = sm;                            // [128][PADW] fp32 C
    unsigned* sHs2  = (unsigned*)(sm + 128 * PADW);  // [128][PADH] half2 (hs pairs)
    unsigned* sNh2  = sHs2 + 128 * PADH;             // half2 (nh pairs)
    unsigned* sCs2  = sNh2 + 128 * PADH;             // half2 (c pairs)
    float2*   redND = (float2*)(sCs2 + 128 * PADH);  // 2 x 512 float2
    float2*   senND = redND + 1024;                  // 512 float2

    const int layer = blockIdx.x >> 6;
    const int b     = blockIdx.x & 63;
    const int tid   = threadIdx.x;
    const int j     = tid & 127;
    const int k     = tid >> 7;
    const int lane  = tid & 31;
    const int p     = k * 32 + lane;
    const bool wrt  = ((tid >> 5) & 3) == 0;   // warps 0,4,8,12 (j-group 0)
    const int lofsM = layer * Hn * Hn;
    const int lofsV = layer * Hn;

    // ---- stage recurrent params: hs/nh fp32 regs, C fp32 in SMEM [j][i]
    float hsig[32], nhm[32];
    {
        float cpart = 0.f, apart = 0.f;
        #pragma unroll
        for (int s = 0; s < 32; ++s) {
            int i   = k * 32 + s;
            int idx = lofsM + i * Hn + j;
            float sg = sigma[idx];
            float m  = mu[idx];
            hsig[s] = 0.5f * sg;
            nhm[s]  = -0.5f * sg * m;
            float c = 0.5f * w[idx] * erev[idx];
            sC[j * PADW + i] = c;
            cpart += c;
            apart += fabsf(c);
        }
        redND[k * 128 + j] = make_float2(cpart, apart);
    }

    // ---- BOTH layers stage layer-1 sensory params (pair-packed half2)
    {
        float csum = 0.f, asum = 0.f;
        #pragma unroll
        for (int s = 0; s < 16; ++s) {
            int i0   = k * 32 + 2 * s;
            int idx0 = i0 * Hn + j;
            int idx1 = idx0 + Hn;
            float sg0 = s_sig[idx0], sg1 = s_sig[idx1];
            float m0  = s_mu[idx0],  m1  = s_mu[idx1];
            __half2 h2 = __floats2half2_rn(0.5f * sg0, 0.5f * sg1);
            __half2 n2 = __floats2half2_rn(-0.5f * sg0 * m0, -0.5f * sg1 * m1);
            sHs2[j * PADH + 16 * k + s] = *reinterpret_cast<unsigned*>(&h2);
            sNh2[j * PADH + 16 * k + s] = *reinterpret_cast<unsigned*>(&n2);
            float c0 = 0.5f * s_w[idx0] * s_ev[idx0];
            float c1 = 0.5f * s_w[idx1] * s_ev[idx1];
            __half2 c2 = __floats2half2_rn(c0, c1);
            sCs2[j * PADH + 16 * k + s] = *reinterpret_cast<unsigned*>(&c2);
            csum += c0 + c1;
            asum += fabsf(c0) + fabsf(c1);
        }
        senND[k * 128 + j] = make_float2(csum, asum);
    }
    __syncthreads();

    // per-p constants (fp32, exact) -- every thread for its p
    float2 c0r = redND[p], c1r = redND[128 + p], c2r = redND[256 + p], c3r = redND[384 + p];
    float cC = c0r.x + c1r.x + c2r.x + c3r.x;
    float cA = c0r.y + c1r.y + c2r.y + c3r.y;
    const float gl    = gleak[lofsV + p];
    const float cmt   = cmv[lofsV + p] * (float)UNF;
    const float baseN = gl * vleak[lofsV + p] + cC;
    const float baseD = cmt + gl + cA + 1e-8f;
    // layer-1 sensory constant sums (producer folds them into its partial)
    float2 s0c = senND[p], s1c = senND[128 + p], s2c = senND[256 + p], s3c = senND[384 + p];
    const float csN = s0c.x + s1c.x + s2c.x + s3c.x;
    const float csA = s0c.y + s1c.y + s2c.y + s3c.y;
    __syncthreads();

    const float4* crow = (const float4*)(sC + j * PADW + 32 * k);    // 8 float4
    const uint4*  hrow = (const uint4*)(sHs2 + j * PADH) + 4 * k;    // 4 x (4 half2)
    const uint4*  nrow = (const uint4*)(sNh2 + j * PADH) + 4 * k;
    const uint4*  srow = (const uint4*)(sCs2 + j * PADH) + 4 * k;

    float vreg = 0.f;   // ALL threads: fp32 recurrent state v_p (redundant x4)

    for (int t = 0; t < Tn; ++t) {
        const int o = (t * Bn + b) * Hn;
        float ns, ds;
        if (layer == 0) {
            float2 nd = ND0[o + p];
            ns = nd.x; ds = nd.y;
        } else {
            // --- acquire producer's t, compute consumer sensory half ---
            if (tid == 0) {
                while (ld_acq(&prog[b]) < t + 1) __nanosleep(64);
            }
            __syncthreads();
            float vload = __ldcg(v1 + o + p);   // warp k lanes: v[32k..32k+32)
            float nsum = 0.f, dsum = 0.f;
            #pragma unroll
            for (int g = 2; g < 4; ++g) {       // i pairs [8..16) => i-slot [16,32)
                uint4 h4 = hrow[g];
                uint4 n4 = nrow[g];
                uint4 c4 = srow[g];
                const __half2* hh = reinterpret_cast<const __half2*>(&h4);
                const __half2* nn = reinterpret_cast<const __half2*>(&n4);
                const __half2* cc = reinterpret_cast<const __half2*>(&c4);
                #pragma unroll
                for (int e = 0; e < 4; ++e) {
                    int s = g * 8 + e * 2;
                    float v0  = __shfl_sync(0xffffffffu, vload, s);
                    float v1s = __shfl_sync(0xffffffffu, vload, s + 1);
                    float2 a = __half22float2(hh[e]);
                    float2 m = __half22float2(nn[e]);
                    float2 c = __half22float2(cc[e]);
                    float g0 = fmaf(v0,  a.x, m.x);
                    float g1 = fmaf(v1s, a.y, m.y);
                    float th0, th1;
                    asm("tanh.approx.f32 %0, %1;" : "=f"(th0) : "f"(g0));
                    asm("tanh.approx.f32 %0, %1;" : "=f"(th1) : "f"(g1));
                    nsum = fmaf(c.x, th0, nsum);
                    dsum = fmaf(fabsf(c.x), th0, dsum);
                    nsum = fmaf(c.y, th1, nsum);
                    dsum = fmaf(fabsf(c.y), th1, dsum);
                }
            }
            senND[k * 128 + j] = make_float2(nsum, dsum);
            __syncthreads();
            float2 q0 = senND[p], q1 = senND[128 + p], q2 = senND[256 + p], q3 = senND[384 + p];
            float2 nd = __ldcg(ND1 + o + p);    // producer partial (incl csN/csA)
            ns = nd.x + q0.x + q1.x + q2.x + q3.x;
            ds = nd.y + q0.y + q1.y + q2.y + q3.y;
        }

        #pragma unroll 1
        for (int u = 0; u < UNF; ++u) {
            const int par = u & 1;
            float num = 0.f, den = 0.f;
            #pragma unroll
            for (int s4 = 0; s4 < 8; ++s4) {
                float4 c4 = crow[s4];
                #pragma unroll
                for (int e = 0; e < 4; ++e) {
                    int s = s4 * 4 + e;
                    float vs = __shfl_sync(0xffffffffu, vreg, s);
                    float arg = fmaf(vs, hsig[s], nhm[s]);
                    float th;
                    asm("tanh.approx.f32 %0, %1;" : "=f"(th) : "f"(arg));
                    float c = (&c4.x)[e];
                    num = fmaf(c, th, num);
                    den = fmaf(fabsf(c), th, den);
                }
            }
            redND[par * 512 + k * 128 + j] = make_float2(num, den);
            __syncthreads();
            // every thread redundantly computes v_p
            const float2* rp = redND + par * 512;
            float2 r0 = rp[p], r1 = rp[128 + p], r2 = rp[256 + p], r3 = rp[384 + p];
            float rn = r0.x + r1.x + r2.x + r3.x;
            float rd = r0.y + r1.y + r2.y + r3.y;
            float tn = rn + ns + baseN + cmt * vreg;
            float td = rd + ds + baseD;
            vreg = __fdividef(tn, td);
        }

        if (layer == 0) {
            // producer sensory HALF: i pairs [0..8) => i-slot [0,16)
            float nsum = 0.f, dsum = 0.f;
            #pragma unroll
            for (int g = 0; g < 2; ++g) {
                uint4 h4 = hrow[g];
                uint4 n4 = nrow[g];
                uint4 c4 = srow[g];
                const __half2* hh = reinterpret_cast<const __half2*>(&h4);
                const __half2* nn = reinterpret_cast<const __half2*>(&n4);
                const __half2* cc = reinterpret_cast<const __half2*>(&c4);
                #pragma unroll
                for (int e = 0; e < 4; ++e) {
                    int s = g * 8 + e * 2;
                    float v0  = __shfl_sync(0xffffffffu, vreg, s);
                    float v1s = __shfl_sync(0xffffffffu, vreg, s + 1);
                    float2 a = __half22float2(hh[e]);
                    float2 m = __half22float2(nn[e]);
                    float2 c = __half22float2(cc[e]);
                    float g0 = fmaf(v0,  a.x, m.x);
                    float g1 = fmaf(v1s, a.y, m.y);
                    float th0, th1;
                    asm("tanh.approx.f32 %0, %1;" : "=f"(th0) : "f"(g0));
                    asm("tanh.approx.f32 %0, %1;" : "=f"(th1) : "f"(g1));
                    nsum = fmaf(c.x, th0, nsum);
                    dsum = fmaf(fabsf(c.x), th0, dsum);
                    nsum = fmaf(c.y, th1, nsum);
                    dsum = fmaf(fabsf(c.y), th1, dsum);
                }
            }
            senND[k * 128 + j] = make_float2(nsum, dsum);
            __syncthreads();
            if (wrt) {
                float2 q0 = senND[p], q1 = senND[128 + p], q2 = senND[256 + p], q3 = senND[384 + p];
                float nn = q0.x + q1.x + q2.x + q3.x + csN;
                float dd = q0.y + q1.y + q2.y + q3.y + csA;
                ND1[o + p] = make_float2(nn, dd);
                v1[o + p]  = vreg;
            }
            __syncthreads();
            // cumulative release: publishes the ND1/v1 stores above
            if (tid == 0) st_rel(&prog[b], t + 1);
        } else {
            if (wrt) h1[o + p] = vreg;
        }
    }
}

// ---------------------------------------------------------------------------
// Head GEMM: out_part = h[64,16384] @ W^T (W = [512,16384]), k-split by 32.
// ---------------------------------------------------------------------------
__global__ __launch_bounds__(128)
void heads_kernel(const float* __restrict__ hseq,
                  const float* __restrict__ Wm, const float* __restrict__ Wl,
                  float* __restrict__ part)
{
    extern __shared__ float sm[];
    float* a_s = sm;               // [128][66] transposed h tile
    float* w_s = sm + 128 * 66;    // [32][128]

    const int tid  = threadIdx.x;
    const int lt   = blockIdx.x;
    const int head = blockIdx.y;
    const int ks   = blockIdx.z;
    const float* W = head ? Wl : Wm;
    const int lat0 = lt * 32;
    const int bg   = tid & 15;
    const int lg   = tid >> 4;

    float acc[4][4];
    #pragma unroll
    for (int a = 0; a < 4; ++a)
        #pragma unroll
        for (int c = 0; c < 4; ++c) acc[a][c] = 0.f;

    for (int t = ks * 4; t < ks * 4 + 4; ++t) {
        __syncthreads();
        const float* src = hseq + t * Bn * Hn;
        #pragma unroll
        for (int r = 0; r < 64; ++r) {
            int idx = r * 128 + tid;
            a_s[(idx & 127) * 66 + (idx >> 7)] = src[idx];
        }
        #pragma unroll
        for (int r = 0; r < 32; ++r)
            w_s[r * 128 + tid] = W[(lat0 + r) * (Tn * Hn) + t * Hn + tid];
        __syncthreads();

        #pragma unroll 4
        for (int jj = 0; jj < 128; ++jj) {
            float2 a01 = *reinterpret_cast<const float2*>(&a_s[jj * 66 + bg * 4]);
            float2 a23 = *reinterpret_cast<const float2*>(&a_s[jj * 66 + bg * 4 + 2]);
            float av[4] = {a01.x, a01.y, a23.x, a23.y};
            float w0 = w_s[(lg * 4 + 0) * 128 + jj];
            float w1 = w_s[(lg * 4 + 1) * 128 + jj];
            float w2 = w_s[(lg * 4 + 2) * 128 + jj];
            float w3 = w_s[(lg * 4 + 3) * 128 + jj];
            #pragma unroll
            for (int bi = 0; bi < 4; ++bi) {
                acc[bi][0] = fmaf(av[bi], w0, acc[bi][0]);
                acc[bi][1] = fmaf(av[bi], w1, acc[bi][1]);
                acc[bi][2] = fmaf(av[bi], w2, acc[bi][2]);
                acc[bi][3] = fmaf(av[bi], w3, acc[bi][3]);
            }
        }
    }
    #pragma unroll
    for (int bi = 0; bi < 4; ++bi)
        #pragma unroll
        for (int li = 0; li < 4; ++li)
            part[(((ks * 2 + head) * Bn) + bg * 4 + bi) * LATn + lat0 + lg * 4 + li]
                = acc[bi][li];
}

// ---------------------------------------------------------------------------
// Epilogue: sum k-split partials, add bias, exp for sigma head.
// ---------------------------------------------------------------------------
__global__ __launch_bounds__(256)
void epilogue_kernel(const float* __restrict__ part,
                     const float* __restrict__ mu_b, const float* __restrict__ ls_b,
                     float* __restrict__ out)
{
    int idx  = blockIdx.x * 256 + threadIdx.x;
    int head = idx >> 15;
    int r    = idx & 32767;
    int lat  = r & 511;
    float s = 0.f;
    #pragma unroll
    for (int ks = 0; ks < 32; ++ks)
        s += part[(ks * 2 + head) * Bn * LATn + r];
    s += head ? ls_b[lat] : mu_b[lat];
    out[idx] = head ? expf(s) : s;
}

// ---------------------------------------------------------------------------
// Launch
// ---------------------------------------------------------------------------
extern "C" void kernel_launch(void* const* d_in, const int* in_sizes, int n_in,
                              void* d_out, int out_size)
{
    const float* x      = (const float*)d_in[0];
    const float* gleak  = (const float*)d_in[1];
    const float* vleak  = (const float*)d_in[2];
    const float* cmv    = (const float*)d_in[3];
    const float* sigma  = (const float*)d_in[4];
    const float* mu_syn = (const float*)d_in[5];
    const float* w      = (const float*)d_in[6];
    const float* erev   = (const float*)d_in[7];
    const float* s_sig  = (const float*)d_in[8];
    const float* s_mu   = (const float*)d_in[9];
    const float* s_w    = (const float*)d_in[10];
    const float* s_ev   = (const float*)d_in[11];
    const float* mu_w   = (const float*)d_in[12];
    const float* mu_b   = (const float*)d_in[13];
    const float* ls_w   = (const float*)d_in[14];
    const float* ls_b   = (const float*)d_in[15];
    float* out = (float*)d_out;

    float2 *ND0, *ND1;
    float *v1, *h1, *part;
    int* prog;
    cudaGetSymbolAddress((void**)&ND0,  g_ND0);
    cudaGetSymbolAddress((void**)&ND1,  g_ND1);
    cudaGetSymbolAddress((void**)&v1,   g_v1);
    cudaGetSymbolAddress((void**)&h1,   g_h1);
    cudaGetSymbolAddress((void**)&part, g_part);
    cudaGetSymbolAddress((void**)&prog, g_prog);

    const int SENS_SMEM = (3 * 128 * PADW + 16 * Hn) * 4;            // 210944 B
    // pipe smem words: C 128*PADW=16896, sensory params 3*128*PADH=26112,
    // redND 2*512 float2 = 2048, senND 512 float2 = 1024  -> 46080 words
    const int PIPE_SMEM = (128 * PADW + 3 * 128 * PADH + 2048 + 1024) * 4;  // 184320 B
    const int GEMM_SMEM = (128 * 66 + 32 * 128) * 4;                 // 50176 B
    cudaFuncSetAttribute(sensory_kernel, cudaFuncAttributeMaxDynamicSharedMemorySize, SENS_SMEM);
    cudaFuncSetAttribute(pipe_kernel,    cudaFuncAttributeMaxDynamicSharedMemorySize, PIPE_SMEM);
    cudaFuncSetAttribute(heads_kernel,   cudaFuncAttributeMaxDynamicSharedMemorySize, GEMM_SMEM);

    init_kernel<<<1, Bn>>>(prog);
    // layer-0 sensory from x [B,T,F]: u[t][b][i] -> stride_t=F, stride_b=T*F
    sensory_kernel<<<512, 256, SENS_SMEM>>>(x, Fn, Tn * Fn,
                                            s_sig, s_mu, s_w, s_ev, ND0);
    // pipelined dual-layer recurrence (layer-1 sensory params offset by H*H)
    pipe_kernel<<<128, 512, PIPE_SMEM>>>(sigma, mu_syn, w, erev, gleak, vleak, cmv,
                                         s_sig + Hn * Hn, s_mu + Hn * Hn,
                                         s_w + Hn * Hn, s_ev + Hn * Hn,
                                         ND0, ND1, v1, h1, prog);
    // heads
    heads_kernel<<<dim3(16, 2, 32), 128, GEMM_SMEM>>>(h1, mu_w, ls_w, part);
    epilogue_kernel<<<(2 * Bn * LATn) / 256, 256>>>(part, mu_b, ls_b, out);
}

// round 16
// speedup vs baseline: 1.0716x; 1.0316x over previous
#include <cuda_runtime.h>
#include <cuda_fp16.h>
#include <cuda_bf16.h>

// Problem constants
#define Bn   64
#define Tn   128
#define Fn   128
#define Hn   128
#define LATn 512
#define UNF  6
#define PADW 132   // fp32 padded row stride (words)
#define PADH 68    // half2-pair padded row stride (u32 words)

// ---------------------------------------------------------------------------
// Device scratch (no allocations allowed)
// ---------------------------------------------------------------------------
__device__ float2 g_ND0[Tn * Bn * Hn];         // layer-0 sensory (num,den)
__device__ float2 g_ND1[Tn * Bn * Hn];         // layer-1 sensory PARTIAL (producer half)
__device__ float  g_v1[Tn * Bn * Hn];          // layer-0 hidden v(t) handoff
__device__ float  g_h1[Tn * Bn * Hn];          // layer-1 hidden seq (final)
__device__ float  g_part[32 * 2 * Bn * LATn];  // head GEMM k-split partials
__device__ int    g_prog[Bn];                  // per-batch pipeline progress

// ---------------------------------------------------------------------------
// helpers
// ---------------------------------------------------------------------------
__device__ __forceinline__ int ld_acq(const int* p) {
    int v;
    asm volatile("ld.global.acquire.gpu.b32 %0, [%1];" : "=r"(v) : "l"(p) : "memory");
    return v;
}
__device__ __forceinline__ void st_rel(int* p, int v) {
    asm volatile("st.global.release.gpu.b32 [%0], %1;" :: "l"(p), "r"(v) : "memory");
}

__global__ void init_kernel(int* prog) { prog[threadIdx.x] = 0; }

// ---------------------------------------------------------------------------
// Layer-0 sensory precompute (full fp32). grid 512 x 256 threads.
// ---------------------------------------------------------------------------
__global__ __launch_bounds__(256, 1)
void sensory_kernel(const float* __restrict__ U, int stride_t, int stride_b,
                    const float* __restrict__ ssig, const float* __restrict__ smu,
                    const float* __restrict__ sw,   const float* __restrict__ sev,
                    float2* __restrict__ ND)
{
    extern __shared__ float sm[];
    float* sHs = sm;                      // [128][PADW]
    float* sNh = sm + 128 * PADW;         // [128][PADW]
    float* sCc = sm + 2 * 128 * PADW;     // [128][PADW]
    float* su  = sm + 3 * 128 * PADW;     // [16][128]

    const int tid   = threadIdx.x;
    const int j     = tid & 127;
    const int half  = tid >> 7;
    const int pair0 = blockIdx.x * 16;

    for (int idx = tid; idx < Hn * Hn; idx += 256) {
        int i  = idx >> 7;
        int jj = idx & 127;
        float sg = ssig[idx];
        float m  = smu[idx];
        sHs[jj * PADW + i] = 0.5f * sg;
        sNh[jj * PADW + i] = -0.5f * sg * m;
        sCc[jj * PADW + i] = 0.5f * sw[idx] * sev[idx];
    }
    for (int idx = tid; idx < 16 * Hn; idx += 256) {
        int p  = idx >> 7;
        int i  = idx & 127;
        int pr = pair0 + p;
        int t  = pr >> 6;
        int b  = pr & 63;
        su[idx] = U[t * stride_t + b * stride_b + i];
    }
    __syncthreads();

    float cC = 0.f, cA = 0.f;
    {
        const float4* cr = (const float4*)(sCc + j * PADW);
        #pragma unroll 8
        for (int q = 0; q < 32; ++q) {
            float4 c4 = cr[q];
            cC += c4.x + c4.y + c4.z + c4.w;
            cA += fabsf(c4.x) + fabsf(c4.y) + fabsf(c4.z) + fabsf(c4.w);
        }
    }

    const float4* hsr = (const float4*)(sHs + j * PADW);
    const float4* nhr = (const float4*)(sNh + j * PADW);
    const float4* ccr = (const float4*)(sCc + j * PADW);

    for (int pg2 = 0; pg2 < 2; ++pg2) {
        const int pg = half * 2 + pg2;
        const float4* u0r = (const float4*)(su + (pg * 4 + 0) * Hn);
        const float4* u1r = (const float4*)(su + (pg * 4 + 1) * Hn);
        const float4* u2r = (const float4*)(su + (pg * 4 + 2) * Hn);
        const float4* u3r = (const float4*)(su + (pg * 4 + 3) * Hn);
        float n0 = cC, n1 = cC, n2 = cC, n3 = cC;
        float d0 = cA, d1 = cA, d2 = cA, d3 = cA;
        #pragma unroll 4
        for (int q = 0; q < 32; ++q) {
            float4 hs = hsr[q], nh = nhr[q], cc = ccr[q];
            float4 u0 = u0r[q], u1 = u1r[q], u2 = u2r[q], u3 = u3r[q];
            #pragma unroll
            for (int e = 0; e < 4; ++e) {
                float hse = (&hs.x)[e];
                float nhe = (&nh.x)[e];
                float c   = (&cc.x)[e];
                float ac  = fabsf(c);
                float t0, t1, t2, t3;
                float a0 = fmaf((&u0.x)[e], hse, nhe);
                float a1 = fmaf((&u1.x)[e], hse, nhe);
                float a2 = fmaf((&u2.x)[e], hse, nhe);
                float a3 = fmaf((&u3.x)[e], hse, nhe);
                asm("tanh.approx.f32 %0, %1;" : "=f"(t0) : "f"(a0));
                asm("tanh.approx.f32 %0, %1;" : "=f"(t1) : "f"(a1));
                asm("tanh.approx.f32 %0, %1;" : "=f"(t2) : "f"(a2));
                asm("tanh.approx.f32 %0, %1;" : "=f"(t3) : "f"(a3));
                n0 = fmaf(c, t0, n0);  d0 = fmaf(ac, t0, d0);
                n1 = fmaf(c, t1, n1);  d1 = fmaf(ac, t1, d1);
                n2 = fmaf(c, t2, n2);  d2 = fmaf(ac, t2, d2);
                n3 = fmaf(c, t3, n3);  d3 = fmaf(ac, t3, d3);
            }
        }
        int o = (pair0 + pg * 4) * Hn + j;
        ND[o]          = make_float2(n0, d0);
        ND[o + Hn]     = make_float2(n1, d1);
        ND[o + 2 * Hn] = make_float2(n2, d2);
        ND[o + 3 * Hn] = make_float2(n3, d3);
    }
}

// ---------------------------------------------------------------------------
// Pipelined dual-layer LTC, full fp32, balanced 6.5 units/side.
// v-distribution via WARP-PRIVATE SMEM broadcast (zero SHFL in hot loop):
// each warp redundantly holds v[32k..32k+32); after the reduce each lane
// stores v_p to its warp's 32-float slot (STS + syncwarp); the next unfold
// reads it back as broadcast LDS.128. Numerically identical to shuffles.
// ---------------------------------------------------------------------------
__global__ __launch_bounds__(512, 1)
void pipe_kernel(const float* __restrict__ sigma, const float* __restrict__ mu,
                 const float* __restrict__ w,     const float* __restrict__ erev,
                 const float* __restrict__ gleak, const float* __restrict__ vleak,
                 const float* __restrict__ cmv,
                 const float* __restrict__ s_sig, const float* __restrict__ s_mu,
                 const float* __restrict__ s_w,   const float* __restrict__ s_ev,
                 const float2* __restrict__ ND0,  float2* __restrict__ ND1,
                 float* __restrict__ v1,          float* __restrict__ h1,
                 int* __restrict__ prog)
{
    extern __shared__ float sm[];
    float*    sC    = sm;                            // [128][PADW] fp32 C
    unsigned* sHs2  = (unsigned*)(sm + 128 * PADW);  // [128][PADH] half2 (hs pairs)
    unsigned* sNh2  = sHs2 + 128 * PADH;             // half2 (nh pairs)
    unsigned* sCs2  = sNh2 + 128 * PADH;             // half2 (c pairs)
    float2*   redND = (float2*)(sCs2 + 128 * PADH);  // 2 x 512 float2
    float2*   senND = redND + 1024;                  // 512 float2
    float*    svbuf = (float*)(senND + 512);         // [16][32] warp-private v
    float*    svext = svbuf + 512;                   // [16][32] consumer vload

    const int layer = blockIdx.x >> 6;
    const int b     = blockIdx.x & 63;
    const int tid   = threadIdx.x;
    const int j     = tid & 127;
    const int k     = tid >> 7;
    const int wid   = tid >> 5;          // warp id 0..15
    const int lane  = tid & 31;
    const int p     = k * 32 + lane;
    const bool wrt  = ((tid >> 5) & 3) == 0;   // warps 0,4,8,12 (j-group 0)
    const int lofsM = layer * Hn * Hn;
    const int lofsV = layer * Hn;

    // ---- stage recurrent params: hs/nh fp32 regs, C fp32 in SMEM [j][i]
    float hsig[32], nhm[32];
    {
        float cpart = 0.f, apart = 0.f;
        #pragma unroll
        for (int s = 0; s < 32; ++s) {
            int i   = k * 32 + s;
            int idx = lofsM + i * Hn + j;
            float sg = sigma[idx];
            float m  = mu[idx];
            hsig[s] = 0.5f * sg;
            nhm[s]  = -0.5f * sg * m;
            float c = 0.5f * w[idx] * erev[idx];
            sC[j * PADW + i] = c;
            cpart += c;
            apart += fabsf(c);
        }
        redND[k * 128 + j] = make_float2(cpart, apart);
    }
    svbuf[wid * 32 + lane] = 0.f;   // initial v state per warp

    // ---- BOTH layers stage layer-1 sensory params (pair-packed half2)
    {
        float csum = 0.f, asum = 0.f;
        #pragma unroll
        for (int s = 0; s < 16; ++s) {
            int i0   = k * 32 + 2 * s;
            int idx0 = i0 * Hn + j;
            int idx1 = idx0 + Hn;
            float sg0 = s_sig[idx0], sg1 = s_sig[idx1];
            float m0  = s_mu[idx0],  m1  = s_mu[idx1];
            __half2 h2 = __floats2half2_rn(0.5f * sg0, 0.5f * sg1);
            __half2 n2 = __floats2half2_rn(-0.5f * sg0 * m0, -0.5f * sg1 * m1);
            sHs2[j * PADH + 16 * k + s] = *reinterpret_cast<unsigned*>(&h2);
            sNh2[j * PADH + 16 * k + s] = *reinterpret_cast<unsigned*>(&n2);
            float c0 = 0.5f * s_w[idx0] * s_ev[idx0];
            float c1 = 0.5f * s_w[idx1] * s_ev[idx1];
            __half2 c2 = __floats2half2_rn(c0, c1);
            sCs2[j * PADH + 16 * k + s] = *reinterpret_cast<unsigned*>(&c2);
            csum += c0 + c1;
            asum += fabsf(c0) + fabsf(c1);
        }
        senND[k * 128 + j] = make_float2(csum, asum);
    }
    __syncthreads();

    // per-p constants (fp32, exact) -- every thread for its p
    float2 c0r = redND[p], c1r = redND[128 + p], c2r = redND[256 + p], c3r = redND[384 + p];
    float cC = c0r.x + c1r.x + c2r.x + c3r.x;
    float cA = c0r.y + c1r.y + c2r.y + c3r.y;
    const float gl    = gleak[lofsV + p];
    const float cmt   = cmv[lofsV + p] * (float)UNF;
    const float baseN = gl * vleak[lofsV + p] + cC;
    const float baseD = cmt + gl + cA + 1e-8f;
    float2 s0c = senND[p], s1c = senND[128 + p], s2c = senND[256 + p], s3c = senND[384 + p];
    const float csN = s0c.x + s1c.x + s2c.x + s3c.x;
    const float csA = s0c.y + s1c.y + s2c.y + s3c.y;
    __syncthreads();

    const float4* crow  = (const float4*)(sC + j * PADW + 32 * k);   // 8 float4
    const uint4*  hrow  = (const uint4*)(sHs2 + j * PADH) + 4 * k;   // 4 x (4 half2)
    const uint4*  nrow  = (const uint4*)(sNh2 + j * PADH) + 4 * k;
    const uint4*  srow  = (const uint4*)(sCs2 + j * PADH) + 4 * k;
    const float4* vrow4 = (const float4*)(svbuf + wid * 32);         // own-warp v
    const float2* vrow2 = (const float2*)(svbuf + wid * 32);
    const float2* xrow2 = (const float2*)(svext + wid * 32);

    float vreg = 0.f;   // ALL threads: fp32 recurrent state v_p (redundant x4)

    for (int t = 0; t < Tn; ++t) {
        const int o = (t * Bn + b) * Hn;
        float ns, ds;
        if (layer == 0) {
            float2 nd = ND0[o + p];
            ns = nd.x; ds = nd.y;
        } else {
            // --- acquire producer's t, compute consumer sensory half ---
            if (tid == 0) {
                while (ld_acq(&prog[b]) < t + 1) __nanosleep(64);
            }
            __syncthreads();
            float vload = __ldcg(v1 + o + p);   // warp k lanes: v[32k..32k+32)
            svext[wid * 32 + lane] = vload;
            __syncwarp();
            float nsum = 0.f, dsum = 0.f;
            #pragma unroll
            for (int g = 2; g < 4; ++g) {       // i-slot [16,32)
                uint4 h4 = hrow[g];
                uint4 n4 = nrow[g];
                uint4 c4 = srow[g];
                const __half2* hh = reinterpret_cast<const __half2*>(&h4);
                const __half2* nn = reinterpret_cast<const __half2*>(&n4);
                const __half2* cc = reinterpret_cast<const __half2*>(&c4);
                #pragma unroll
                for (int e = 0; e < 4; ++e) {
                    float2 v2 = xrow2[g * 4 + e];   // {v[s], v[s+1]} broadcast
                    float2 a = __half22float2(hh[e]);
                    float2 m = __half22float2(nn[e]);
                    float2 c = __half22float2(cc[e]);
                    float g0 = fmaf(v2.x, a.x, m.x);
                    float g1 = fmaf(v2.y, a.y, m.y);
                    float th0, th1;
                    asm("tanh.approx.f32 %0, %1;" : "=f"(th0) : "f"(g0));
                    asm("tanh.approx.f32 %0, %1;" : "=f"(th1) : "f"(g1));
                    nsum = fmaf(c.x, th0, nsum);
                    dsum = fmaf(fabsf(c.x), th0, dsum);
                    nsum = fmaf(c.y, th1, nsum);
                    dsum = fmaf(fabsf(c.y), th1, dsum);
                }
            }
            senND[k * 128 + j] = make_float2(nsum, dsum);
            __syncthreads();
            float2 q0 = senND[p], q1 = senND[128 + p], q2 = senND[256 + p], q3 = senND[384 + p];
            float2 nd = __ldcg(ND1 + o + p);    // producer partial (incl csN/csA)
            ns = nd.x + q0.x + q1.x + q2.x + q3.x;
            ds = nd.y + q0.y + q1.y + q2.y + q3.y;
        }

        #pragma unroll 1
        for (int u = 0; u < UNF; ++u) {
            const int par = u & 1;
            float num = 0.f, den = 0.f;
            #pragma unroll
            for (int s4 = 0; s4 < 8; ++s4) {
                float4 v4 = vrow4[s4];          // broadcast, own-warp v state
                float4 c4 = crow[s4];
                #pragma unroll
                for (int e = 0; e < 4; ++e) {
                    int s = s4 * 4 + e;
                    float arg = fmaf((&v4.x)[e], hsig[s], nhm[s]);
                    float th;
                    asm("tanh.approx.f32 %0, %1;" : "=f"(th) : "f"(arg));
                    float c = (&c4.x)[e];
                    num = fmaf(c, th, num);
                    den = fmaf(fabsf(c), th, den);
                }
            }
            redND[par * 512 + k * 128 + j] = make_float2(num, den);
            __syncthreads();
            // every thread redundantly computes v_p
            const float2* rp = redND + par * 512;
            float2 r0 = rp[p], r1 = rp[128 + p], r2 = rp[256 + p], r3 = rp[384 + p];
            float rn = r0.x + r1.x + r2.x + r3.x;
            float rd = r0.y + r1.y + r2.y + r3.y;
            float tn = rn + ns + baseN + cmt * vreg;
            float td = rd + ds + baseD;
            vreg = __fdividef(tn, td);
            svbuf[wid * 32 + lane] = vreg;
            __syncwarp();
        }

        if (layer == 0) {
            // producer sensory HALF: i-slot [0,16); v state already in svbuf
            float nsum = 0.f, dsum = 0.f;
            #pragma unroll
            for (int g = 0; g < 2; ++g) {
                uint4 h4 = hrow[g];
                uint4 n4 = nrow[g];
                uint4 c4 = srow[g];
                const __half2* hh = reinterpret_cast<const __half2*>(&h4);
                const __half2* nn = reinterpret_cast<const __half2*>(&n4);
                const __half2* cc = reinterpret_cast<const __half2*>(&c4);
                #pragma unroll
                for (int e = 0; e < 4; ++e) {
                    float2 v2 = vrow2[g * 4 + e];
                    float2 a = __half22float2(hh[e]);
                    float2 m = __half22float2(nn[e]);
                    float2 c = __half22float2(cc[e]);
                    float g0 = fmaf(v2.x, a.x, m.x);
                    float g1 = fmaf(v2.y, a.y, m.y);
                    float th0, th1;
                    asm("tanh.approx.f32 %0, %1;" : "=f"(th0) : "f"(g0));
                    asm("tanh.approx.f32 %0, %1;" : "=f"(th1) : "f"(g1));
                    nsum = fmaf(c.x, th0, nsum);
                    dsum = fmaf(fabsf(c.x), th0, dsum);
                    nsum = fmaf(c.y, th1, nsum);
                    dsum = fmaf(fabsf(c.y), th1, dsum);
                }
            }
            senND[k * 128 + j] = make_float2(nsum, dsum);
            __syncthreads();
            if (wrt) {
                float2 q0 = senND[p], q1 = senND[128 + p], q2 = senND[256 + p], q3 = senND[384 + p];
                float nn = q0.x + q1.x + q2.x + q3.x + csN;
                float dd = q0.y + q1.y + q2.y + q3.y + csA;
                ND1[o + p] = make_float2(nn, dd);
                v1[o + p]  = vreg;
            }
            __syncthreads();
            // cumulative release publishes the ND1/v1 stores above
            if (tid == 0) st_rel(&prog[b], t + 1);
        } else {
            if (wrt) h1[o + p] = vreg;
        }
    }
}

// ---------------------------------------------------------------------------
// Head GEMM: out_part = h[64,16384] @ W^T (W = [512,16384]), k-split by 32.
// ---------------------------------------------------------------------------
__global__ __launch_bounds__(128)
void heads_kernel(const float* __restrict__ hseq,
                  const float* __restrict__ Wm, const float* __restrict__ Wl,
                  float* __restrict__ part)
{
    extern __shared__ float sm[];
    float* a_s = sm;               // [128][66] transposed h tile
    float* w_s = sm + 128 * 66;    // [32][128]

    const int tid  = threadIdx.x;
    const int lt   = blockIdx.x;
    const int head = blockIdx.y;
    const int ks   = blockIdx.z;
    const float* W = head ? Wl : Wm;
    const int lat0 = lt * 32;
    const int bg   = tid & 15;
    const int lg   = tid >> 4;

    float acc[4][4];
    #pragma unroll
    for (int a = 0; a < 4; ++a)
        #pragma unroll
        for (int c = 0; c < 4; ++c) acc[a][c] = 0.f;

    for (int t = ks * 4; t < ks * 4 + 4; ++t) {
        __syncthreads();
        const float* src = hseq + t * Bn * Hn;
        #pragma unroll
        for (int r = 0; r < 64; ++r) {
            int idx = r * 128 + tid;
            a_s[(idx & 127) * 66 + (idx >> 7)] = src[idx];
        }
        #pragma unroll
        for (int r = 0; r < 32; ++r)
            w_s[r * 128 + tid] = W[(lat0 + r) * (Tn * Hn) + t * Hn + tid];
        __syncthreads();

        #pragma unroll 4
        for (int jj = 0; jj < 128; ++jj) {
            float2 a01 = *reinterpret_cast<const float2*>(&a_s[jj * 66 + bg * 4]);
            float2 a23 = *reinterpret_cast<const float2*>(&a_s[jj * 66 + bg * 4 + 2]);
            float av[4] = {a01.x, a01.y, a23.x, a23.y};
            float w0 = w_s[(lg * 4 + 0) * 128 + jj];
            float w1 = w_s[(lg * 4 + 1) * 128 + jj];
            float w2 = w_s[(lg * 4 + 2) * 128 + jj];
            float w3 = w_s[(lg * 4 + 3) * 128 + jj];
            #pragma unroll
            for (int bi = 0; bi < 4; ++bi) {
                acc[bi][0] = fmaf(av[bi], w0, acc[bi][0]);
                acc[bi][1] = fmaf(av[bi], w1, acc[bi][1]);
                acc[bi][2] = fmaf(av[bi], w2, acc[bi][2]);
                acc[bi][3] = fmaf(av[bi], w3, acc[bi][3]);
            }
        }
    }
    #pragma unroll
    for (int bi = 0; bi < 4; ++bi)
        #pragma unroll
        for (int li = 0; li < 4; ++li)
            part[(((ks * 2 + head) * Bn) + bg * 4 + bi) * LATn + lat0 + lg * 4 + li]
                = acc[bi][li];
}

// ---------------------------------------------------------------------------
// Epilogue: sum k-split partials, add bias, exp for sigma head.
// ---------------------------------------------------------------------------
__global__ __launch_bounds__(256)
void epilogue_kernel(const float* __restrict__ part,
                     const float* __restrict__ mu_b, const float* __restrict__ ls_b,
                     float* __restrict__ out)
{
    int idx  = blockIdx.x * 256 + threadIdx.x;
    int head = idx >> 15;
    int r    = idx & 32767;
    int lat  = r & 511;
    float s = 0.f;
    #pragma unroll
    for (int ks = 0; ks < 32; ++ks)
        s += part[(ks * 2 + head) * Bn * LATn + r];
    s += head ? ls_b[lat] : mu_b[lat];
    out[idx] = head ? expf(s) : s;
}

// ---------------------------------------------------------------------------
// Launch
// ---------------------------------------------------------------------------
extern "C" void kernel_launch(void* const* d_in, const int* in_sizes, int n_in,
                              void* d_out, int out_size)
{
    const float* x      = (const float*)d_in[0];
    const float* gleak  = (const float*)d_in[1];
    const float* vleak  = (const float*)d_in[2];
    const float* cmv    = (const float*)d_in[3];
    const float* sigma  = (const float*)d_in[4];
    const float* mu_syn = (const float*)d_in[5];
    const float* w      = (const float*)d_in[6];
    const float* erev   = (const float*)d_in[7];
    const float* s_sig  = (const float*)d_in[8];
    const float* s_mu   = (const float*)d_in[9];
    const float* s_w    = (const float*)d_in[10];
    const float* s_ev   = (const float*)d_in[11];
    const float* mu_w   = (const float*)d_in[12];
    const float* mu_b   = (const float*)d_in[13];
    const float* ls_w   = (const float*)d_in[14];
    const float* ls_b   = (const float*)d_in[15];
    float* out = (float*)d_out;

    float2 *ND0, *ND1;
    float *v1, *h1, *part;
    int* prog;
    cudaGetSymbolAddress((void**)&ND0,  g_ND0);
    cudaGetSymbolAddress((void**)&ND1,  g_ND1);
    cudaGetSymbolAddress((void**)&v1,   g_v1);
    cudaGetSymbolAddress((void**)&h1,   g_h1);
    cudaGetSymbolAddress((void**)&part, g_part);
    cudaGetSymbolAddress((void**)&prog, g_prog);

    const int SENS_SMEM = (3 * 128 * PADW + 16 * Hn) * 4;            // 210944 B
    // pipe smem words: C 16896, sensory params 26112, redND 2048,
    // senND 1024, svbuf 512, svext 512 -> 47104 words
    const int PIPE_SMEM = (128 * PADW + 3 * 128 * PADH + 2048 + 1024 + 1024) * 4;  // 188416 B
    const int GEMM_SMEM = (128 * 66 + 32 * 128) * 4;                 // 50176 B
    cudaFuncSetAttribute(sensory_kernel, cudaFuncAttributeMaxDynamicSharedMemorySize, SENS_SMEM);
    cudaFuncSetAttribute(pipe_kernel,    cudaFuncAttributeMaxDynamicSharedMemorySize, PIPE_SMEM);
    cudaFuncSetAttribute(heads_kernel,   cudaFuncAttributeMaxDynamicSharedMemorySize, GEMM_SMEM);

    init_kernel<<<1, Bn>>>(prog);
    // layer-0 sensory from x [B,T,F]: u[t][b][i] -> stride_t=F, stride_b=T*F
    sensory_kernel<<<512, 256, SENS_SMEM>>>(x, Fn, Tn * Fn,
                                            s_sig, s_mu, s_w, s_ev, ND0);
    // pipelined dual-layer recurrence (layer-1 sensory params offset by H*H)
    pipe_kernel<<<128, 512, PIPE_SMEM>>>(sigma, mu_syn, w, erev, gleak, vleak, cmv,
                                         s_sig + Hn * Hn, s_mu + Hn * Hn,
                                         s_w + Hn * Hn, s_ev + Hn * Hn,
                                         ND0, ND1, v1, h1, prog);
    // heads
    heads_kernel<<<dim3(16, 2, 32), 128, GEMM_SMEM>>>(h1, mu_w, ls_w, part);
    epilogue_kernel<<<(2 * Bn * LATn) / 256, 256>>>(part, mu_b, ls_b, out);
}

// round 17
// speedup vs baseline: 1.0786x; 1.0065x over previous
#include <cuda_runtime.h>
#include <cuda_fp16.h>
#include <cuda_bf16.h>

// Problem constants
#define Bn   64
#define Tn   128
#define Fn   128
#define Hn   128
#define LATn 512
#define UNF  6
#define PADW 132   // fp32 padded row stride (words)
#define PADH 68    // half2-pair padded row stride (u32 words)

// ---------------------------------------------------------------------------
// Device scratch (no allocations allowed)
// ---------------------------------------------------------------------------
__device__ float2 g_ND0[Tn * Bn * Hn];         // layer-0 sensory (num,den)
__device__ float2 g_ND1[Tn * Bn * Hn];         // layer-1 sensory PARTIAL (producer half)
__device__ float  g_v1[Tn * Bn * Hn];          // layer-0 hidden v(t) handoff
__device__ float  g_h1[Tn * Bn * Hn];          // layer-1 hidden seq (final)
__device__ float  g_part[32 * 2 * Bn * LATn];  // head GEMM k-split partials
__device__ int    g_prog[Bn];                  // per-batch pipeline progress

// ---------------------------------------------------------------------------
// helpers
// ---------------------------------------------------------------------------
__device__ __forceinline__ int ld_acq(const int* p) {
    int v;
    asm volatile("ld.global.acquire.gpu.b32 %0, [%1];" : "=r"(v) : "l"(p) : "memory");
    return v;
}
__device__ __forceinline__ void st_rel(int* p, int v) {
    asm volatile("st.global.release.gpu.b32 [%0], %1;" :: "l"(p), "r"(v) : "memory");
}

__global__ void init_kernel(int* prog) { prog[threadIdx.x] = 0; }

// ---------------------------------------------------------------------------
// Layer-0 sensory precompute (full fp32). grid 512 x 256 threads.
// ---------------------------------------------------------------------------
__global__ __launch_bounds__(256, 1)
void sensory_kernel(const float* __restrict__ U, int stride_t, int stride_b,
                    const float* __restrict__ ssig, const float* __restrict__ smu,
                    const float* __restrict__ sw,   const float* __restrict__ sev,
                    float2* __restrict__ ND)
{
    extern __shared__ float sm[];
    float* sHs = sm;                      // [128][PADW]
    float* sNh = sm + 128 * PADW;         // [128][PADW]
    float* sCc = sm + 2 * 128 * PADW;     // [128][PADW]
    float* su  = sm + 3 * 128 * PADW;     // [16][128]

    const int tid   = threadIdx.x;
    const int j     = tid & 127;
    const int half  = tid >> 7;
    const int pair0 = blockIdx.x * 16;

    for (int idx = tid; idx < Hn * Hn; idx += 256) {
        int i  = idx >> 7;
        int jj = idx & 127;
        float sg = ssig[idx];
        float m  = smu[idx];
        sHs[jj * PADW + i] = 0.5f * sg;
        sNh[jj * PADW + i] = -0.5f * sg * m;
        sCc[jj * PADW + i] = 0.5f * sw[idx] * sev[idx];
    }
    for (int idx = tid; idx < 16 * Hn; idx += 256) {
        int p  = idx >> 7;
        int i  = idx & 127;
        int pr = pair0 + p;
        int t  = pr >> 6;
        int b  = pr & 63;
        su[idx] = U[t * stride_t + b * stride_b + i];
    }
    __syncthreads();

    float cC = 0.f, cA = 0.f;
    {
        const float4* cr = (const float4*)(sCc + j * PADW);
        #pragma unroll 8
        for (int q = 0; q < 32; ++q) {
            float4 c4 = cr[q];
            cC += c4.x + c4.y + c4.z + c4.w;
            cA += fabsf(c4.x) + fabsf(c4.y) + fabsf(c4.z) + fabsf(c4.w);
        }
    }

    const float4* hsr = (const float4*)(sHs + j * PADW);
    const float4* nhr = (const float4*)(sNh + j * PADW);
    const float4* ccr = (const float4*)(sCc + j * PADW);

    for (int pg2 = 0; pg2 < 2; ++pg2) {
        const int pg = half * 2 + pg2;
        const float4* u0r = (const float4*)(su + (pg * 4 + 0) * Hn);
        const float4* u1r = (const float4*)(su + (pg * 4 + 1) * Hn);
        const float4* u2r = (const float4*)(su + (pg * 4 + 2) * Hn);
        const float4* u3r = (const float4*)(su + (pg * 4 + 3) * Hn);
        float n0 = cC, n1 = cC, n2 = cC, n3 = cC;
        float d0 = cA, d1 = cA, d2 = cA, d3 = cA;
        #pragma unroll 4
        for (int q = 0; q < 32; ++q) {
            float4 hs = hsr[q], nh = nhr[q], cc = ccr[q];
            float4 u0 = u0r[q], u1 = u1r[q], u2 = u2r[q], u3 = u3r[q];
            #pragma unroll
            for (int e = 0; e < 4; ++e) {
                float hse = (&hs.x)[e];
                float nhe = (&nh.x)[e];
                float c   = (&cc.x)[e];
                float ac  = fabsf(c);
                float t0, t1, t2, t3;
                float a0 = fmaf((&u0.x)[e], hse, nhe);
                float a1 = fmaf((&u1.x)[e], hse, nhe);
                float a2 = fmaf((&u2.x)[e], hse, nhe);
                float a3 = fmaf((&u3.x)[e], hse, nhe);
                asm("tanh.approx.f32 %0, %1;" : "=f"(t0) : "f"(a0));
                asm("tanh.approx.f32 %0, %1;" : "=f"(t1) : "f"(a1));
                asm("tanh.approx.f32 %0, %1;" : "=f"(t2) : "f"(a2));
                asm("tanh.approx.f32 %0, %1;" : "=f"(t3) : "f"(a3));
                n0 = fmaf(c, t0, n0);  d0 = fmaf(ac, t0, d0);
                n1 = fmaf(c, t1, n1);  d1 = fmaf(ac, t1, d1);
                n2 = fmaf(c, t2, n2);  d2 = fmaf(ac, t2, d2);
                n3 = fmaf(c, t3, n3);  d3 = fmaf(ac, t3, d3);
            }
        }
        int o = (pair0 + pg * 4) * Hn + j;
        ND[o]          = make_float2(n0, d0);
        ND[o + Hn]     = make_float2(n1, d1);
        ND[o + 2 * Hn] = make_float2(n2, d2);
        ND[o + 3 * Hn] = make_float2(n3, d3);
    }
}

// ---------------------------------------------------------------------------
// Pipelined dual-layer LTC, full fp32, balanced 6.5 units/side.
// v-distribution via warp-private SMEM broadcast (round-16 structure,
// unchanged).
// ---------------------------------------------------------------------------
__global__ __launch_bounds__(512, 1)
void pipe_kernel(const float* __restrict__ sigma, const float* __restrict__ mu,
                 const float* __restrict__ w,     const float* __restrict__ erev,
                 const float* __restrict__ gleak, const float* __restrict__ vleak,
                 const float* __restrict__ cmv,
                 const float* __restrict__ s_sig, const float* __restrict__ s_mu,
                 const float* __restrict__ s_w,   const float* __restrict__ s_ev,
                 const float2* __restrict__ ND0,  float2* __restrict__ ND1,
                 float* __restrict__ v1,          float* __restrict__ h1,
                 int* __restrict__ prog)
{
    extern __shared__ float sm[];
    float*    sC    = sm;                            // [128][PADW] fp32 C
    unsigned* sHs2  = (unsigned*)(sm + 128 * PADW);  // [128][PADH] half2 (hs pairs)
    unsigned* sNh2  = sHs2 + 128 * PADH;             // half2 (nh pairs)
    unsigned* sCs2  = sNh2 + 128 * PADH;             // half2 (c pairs)
    float2*   redND = (float2*)(sCs2 + 128 * PADH);  // 2 x 512 float2
    float2*   senND = redND + 1024;                  // 512 float2
    float*    svbuf = (float*)(senND + 512);         // [16][32] warp-private v
    float*    svext = svbuf + 512;                   // [16][32] consumer vload

    const int layer = blockIdx.x >> 6;
    const int b     = blockIdx.x & 63;
    const int tid   = threadIdx.x;
    const int j     = tid & 127;
    const int k     = tid >> 7;
    const int wid   = tid >> 5;          // warp id 0..15
    const int lane  = tid & 31;
    const int p     = k * 32 + lane;
    const bool wrt  = ((tid >> 5) & 3) == 0;   // warps 0,4,8,12 (j-group 0)
    const int lofsM = layer * Hn * Hn;
    const int lofsV = layer * Hn;

    // ---- stage recurrent params: hs/nh fp32 regs, C fp32 in SMEM [j][i]
    float hsig[32], nhm[32];
    {
        float cpart = 0.f, apart = 0.f;
        #pragma unroll
        for (int s = 0; s < 32; ++s) {
            int i   = k * 32 + s;
            int idx = lofsM + i * Hn + j;
            float sg = sigma[idx];
            float m  = mu[idx];
            hsig[s] = 0.5f * sg;
            nhm[s]  = -0.5f * sg * m;
            float c = 0.5f * w[idx] * erev[idx];
            sC[j * PADW + i] = c;
            cpart += c;
            apart += fabsf(c);
        }
        redND[k * 128 + j] = make_float2(cpart, apart);
    }
    svbuf[wid * 32 + lane] = 0.f;   // initial v state per warp

    // ---- BOTH layers stage layer-1 sensory params (pair-packed half2)
    {
        float csum = 0.f, asum = 0.f;
        #pragma unroll
        for (int s = 0; s < 16; ++s) {
            int i0   = k * 32 + 2 * s;
            int idx0 = i0 * Hn + j;
            int idx1 = idx0 + Hn;
            float sg0 = s_sig[idx0], sg1 = s_sig[idx1];
            float m0  = s_mu[idx0],  m1  = s_mu[idx1];
            __half2 h2 = __floats2half2_rn(0.5f * sg0, 0.5f * sg1);
            __half2 n2 = __floats2half2_rn(-0.5f * sg0 * m0, -0.5f * sg1 * m1);
            sHs2[j * PADH + 16 * k + s] = *reinterpret_cast<unsigned*>(&h2);
            sNh2[j * PADH + 16 * k + s] = *reinterpret_cast<unsigned*>(&n2);
            float c0 = 0.5f * s_w[idx0] * s_ev[idx0];
            float c1 = 0.5f * s_w[idx1] * s_ev[idx1];
            __half2 c2 = __floats2half2_rn(c0, c1);
            sCs2[j * PADH + 16 * k + s] = *reinterpret_cast<unsigned*>(&c2);
            csum += c0 + c1;
            asum += fabsf(c0) + fabsf(c1);
        }
        senND[k * 128 + j] = make_float2(csum, asum);
    }
    __syncthreads();

    // per-p constants (fp32, exact) -- every thread for its p
    float2 c0r = redND[p], c1r = redND[128 + p], c2r = redND[256 + p], c3r = redND[384 + p];
    float cC = c0r.x + c1r.x + c2r.x + c3r.x;
    float cA = c0r.y + c1r.y + c2r.y + c3r.y;
    const float gl    = gleak[lofsV + p];
    const float cmt   = cmv[lofsV + p] * (float)UNF;
    const float baseN = gl * vleak[lofsV + p] + cC;
    const float baseD = cmt + gl + cA + 1e-8f;
    float2 s0c = senND[p], s1c = senND[128 + p], s2c = senND[256 + p], s3c = senND[384 + p];
    const float csN = s0c.x + s1c.x + s2c.x + s3c.x;
    const float csA = s0c.y + s1c.y + s2c.y + s3c.y;
    __syncthreads();

    const float4* crow  = (const float4*)(sC + j * PADW + 32 * k);   // 8 float4
    const uint4*  hrow  = (const uint4*)(sHs2 + j * PADH) + 4 * k;   // 4 x (4 half2)
    const uint4*  nrow  = (const uint4*)(sNh2 + j * PADH) + 4 * k;
    const uint4*  srow  = (const uint4*)(sCs2 + j * PADH) + 4 * k;
    const float4* vrow4 = (const float4*)(svbuf + wid * 32);         // own-warp v
    const float2* vrow2 = (const float2*)(svbuf + wid * 32);
    const float2* xrow2 = (const float2*)(svext + wid * 32);

    float vreg = 0.f;   // ALL threads: fp32 recurrent state v_p (redundant x4)

    for (int t = 0; t < Tn; ++t) {
        const int o = (t * Bn + b) * Hn;
        float ns, ds;
        if (layer == 0) {
            float2 nd = ND0[o + p];
            ns = nd.x; ds = nd.y;
        } else {
            // --- acquire producer's t, compute consumer sensory half ---
            if (tid == 0) {
                while (ld_acq(&prog[b]) < t + 1) __nanosleep(64);
            }
            __syncthreads();
            float vload = __ldcg(v1 + o + p);   // warp k lanes: v[32k..32k+32)
            svext[wid * 32 + lane] = vload;
            __syncwarp();
            float nsum = 0.f, dsum = 0.f;
            #pragma unroll
            for (int g = 2; g < 4; ++g) {       // i-slot [16,32)
                uint4 h4 = hrow[g];
                uint4 n4 = nrow[g];
                uint4 c4 = srow[g];
                const __half2* hh = reinterpret_cast<const __half2*>(&h4);
                const __half2* nn = reinterpret_cast<const __half2*>(&n4);
                const __half2* cc = reinterpret_cast<const __half2*>(&c4);
                #pragma unroll
                for (int e = 0; e < 4; ++e) {
                    float2 v2 = xrow2[g * 4 + e];   // {v[s], v[s+1]} broadcast
                    float2 a = __half22float2(hh[e]);
                    float2 m = __half22float2(nn[e]);
                    float2 c = __half22float2(cc[e]);
                    float g0 = fmaf(v2.x, a.x, m.x);
                    float g1 = fmaf(v2.y, a.y, m.y);
                    float th0, th1;
                    asm("tanh.approx.f32 %0, %1;" : "=f"(th0) : "f"(g0));
                    asm("tanh.approx.f32 %0, %1;" : "=f"(th1) : "f"(g1));
                    nsum = fmaf(c.x, th0, nsum);
                    dsum = fmaf(fabsf(c.x), th0, dsum);
                    nsum = fmaf(c.y, th1, nsum);
                    dsum = fmaf(fabsf(c.y), th1, dsum);
                }
            }
            senND[k * 128 + j] = make_float2(nsum, dsum);
            __syncthreads();
            float2 q0 = senND[p], q1 = senND[128 + p], q2 = senND[256 + p], q3 = senND[384 + p];
            float2 nd = __ldcg(ND1 + o + p);    // producer partial (incl csN/csA)
            ns = nd.x + q0.x + q1.x + q2.x + q3.x;
            ds = nd.y + q0.y + q1.y + q2.y + q3.y;
        }

        #pragma unroll 1
        for (int u = 0; u < UNF; ++u) {
            const int par = u & 1;
            float num = 0.f, den = 0.f;
            #pragma unroll
            for (int s4 = 0; s4 < 8; ++s4) {
                float4 v4 = vrow4[s4];          // broadcast, own-warp v state
                float4 c4 = crow[s4];
                #pragma unroll
                for (int e = 0; e < 4; ++e) {
                    int s = s4 * 4 + e;
                    float arg = fmaf((&v4.x)[e], hsig[s], nhm[s]);
                    float th;
                    asm("tanh.approx.f32 %0, %1;" : "=f"(th) : "f"(arg));
                    float c = (&c4.x)[e];
                    num = fmaf(c, th, num);
                    den = fmaf(fabsf(c), th, den);
                }
            }
            redND[par * 512 + k * 128 + j] = make_float2(num, den);
            __syncthreads();
            // every thread redundantly computes v_p
            const float2* rp = redND + par * 512;
            float2 r0 = rp[p], r1 = rp[128 + p], r2 = rp[256 + p], r3 = rp[384 + p];
            float rn = r0.x + r1.x + r2.x + r3.x;
            float rd = r0.y + r1.y + r2.y + r3.y;
            float tn = rn + ns + baseN + cmt * vreg;
            float td = rd + ds + baseD;
            vreg = __fdividef(tn, td);
            svbuf[wid * 32 + lane] = vreg;
            __syncwarp();
        }

        if (layer == 0) {
            // producer sensory HALF: i-slot [0,16); v state already in svbuf
            float nsum = 0.f, dsum = 0.f;
            #pragma unroll
            for (int g = 0; g < 2; ++g) {
                uint4 h4 = hrow[g];
                uint4 n4 = nrow[g];
                uint4 c4 = srow[g];
                const __half2* hh = reinterpret_cast<const __half2*>(&h4);
                const __half2* nn = reinterpret_cast<const __half2*>(&n4);
                const __half2* cc = reinterpret_cast<const __half2*>(&c4);
                #pragma unroll
                for (int e = 0; e < 4; ++e) {
                    float2 v2 = vrow2[g * 4 + e];
                    float2 a = __half22float2(hh[e]);
                    float2 m = __half22float2(nn[e]);
                    float2 c = __half22float2(cc[e]);
                    float g0 = fmaf(v2.x, a.x, m.x);
                    float g1 = fmaf(v2.y, a.y, m.y);
                    float th0, th1;
                    asm("tanh.approx.f32 %0, %1;" : "=f"(th0) : "f"(g0));
                    asm("tanh.approx.f32 %0, %1;" : "=f"(th1) : "f"(g1));
                    nsum = fmaf(c.x, th0, nsum);
                    dsum = fmaf(fabsf(c.x), th0, dsum);
                    nsum = fmaf(c.y, th1, nsum);
                    dsum = fmaf(fabsf(c.y), th1, dsum);
                }
            }
            senND[k * 128 + j] = make_float2(nsum, dsum);
            __syncthreads();
            if (wrt) {
                float2 q0 = senND[p], q1 = senND[128 + p], q2 = senND[256 + p], q3 = senND[384 + p];
                float nn = q0.x + q1.x + q2.x + q3.x + csN;
                float dd = q0.y + q1.y + q2.y + q3.y + csA;
                ND1[o + p] = make_float2(nn, dd);
                v1[o + p]  = vreg;
            }
            __syncthreads();
            // cumulative release publishes the ND1/v1 stores above
            if (tid == 0) st_rel(&prog[b], t + 1);
        } else {
            if (wrt) h1[o + p] = vreg;
        }
    }
}

// ---------------------------------------------------------------------------
// Head GEMM: out_part = h[64,16384] @ W^T (W = [512,16384]), k-split by 32.
// Vectorized SMEM: a_s [jj][68] (aligned LDS.128 of 4 batches),
// w_t transposed [jj][36] (aligned LDS.128 of 4 lats).
// Inner loop: 2 LDS.128 + 16 FMA per jj (was 6 LDS).
// ---------------------------------------------------------------------------
__global__ __launch_bounds__(128)
void heads_kernel(const float* __restrict__ hseq,
                  const float* __restrict__ Wm, const float* __restrict__ Wl,
                  float* __restrict__ part)
{
    extern __shared__ float sm[];
    float* a_s = sm;               // [128][68] transposed h tile (b contiguous)
    float* w_t = sm + 128 * 68;    // [128][36] transposed W tile (lat contiguous)

    const int tid  = threadIdx.x;
    const int lt   = blockIdx.x;
    const int head = blockIdx.y;
    const int ks   = blockIdx.z;
    const float* W = head ? Wl : Wm;
    const int lat0 = lt * 32;
    const int bg   = tid & 15;
    const int lg   = tid >> 4;

    float acc[4][4];
    #pragma unroll
    for (int a = 0; a < 4; ++a)
        #pragma unroll
        for (int c = 0; c < 4; ++c) acc[a][c] = 0.f;

    for (int t = ks * 4; t < ks * 4 + 4; ++t) {
        __syncthreads();
        const float* src = hseq + t * Bn * Hn;
        // a_s[j][b] = h[b][j], row stride 68 (272B, 16B-aligned rows)
        #pragma unroll
        for (int r = 0; r < 64; ++r)
            a_s[tid * 68 + r] = src[r * 128 + tid];
        // w_t[jj][r] = W[lat0+r][t*128+jj], row stride 36 (144B, 16B-aligned)
        #pragma unroll
        for (int r = 0; r < 32; ++r)
            w_t[tid * 36 + r] = W[(lat0 + r) * (Tn * Hn) + t * Hn + tid];
        __syncthreads();

        #pragma unroll 4
        for (int jj = 0; jj < 128; ++jj) {
            float4 av = *reinterpret_cast<const float4*>(&a_s[jj * 68 + bg * 4]);
            float4 wv = *reinterpret_cast<const float4*>(&w_t[jj * 36 + lg * 4]);
            #pragma unroll
            for (int bi = 0; bi < 4; ++bi) {
                float a = (&av.x)[bi];
                acc[bi][0] = fmaf(a, wv.x, acc[bi][0]);
                acc[bi][1] = fmaf(a, wv.y, acc[bi][1]);
                acc[bi][2] = fmaf(a, wv.z, acc[bi][2]);
                acc[bi][3] = fmaf(a, wv.w, acc[bi][3]);
            }
        }
    }
    #pragma unroll
    for (int bi = 0; bi < 4; ++bi)
        #pragma unroll
        for (int li = 0; li < 4; ++li)
            part[(((ks * 2 + head) * Bn) + bg * 4 + bi) * LATn + lat0 + lg * 4 + li]
                = acc[bi][li];
}

// ---------------------------------------------------------------------------
// Epilogue: sum k-split partials, add bias, exp for sigma head.
// ---------------------------------------------------------------------------
__global__ __launch_bounds__(256)
void epilogue_kernel(const float* __restrict__ part,
                     const float* __restrict__ mu_b, const float* __restrict__ ls_b,
                     float* __restrict__ out)
{
    int idx  = blockIdx.x * 256 + threadIdx.x;
    int head = idx >> 15;
    int r    = idx & 32767;
    int lat  = r & 511;
    float s = 0.f;
    #pragma unroll
    for (int ks = 0; ks < 32; ++ks)
        s += part[(ks * 2 + head) * Bn * LATn + r];
    s += head ? ls_b[lat] : mu_b[lat];
    out[idx] = head ? expf(s) : s;
}

// ---------------------------------------------------------------------------
// Launch
// ---------------------------------------------------------------------------
extern "C" void kernel_launch(void* const* d_in, const int* in_sizes, int n_in,
                              void* d_out, int out_size)
{
    const float* x      = (const float*)d_in[0];
    const float* gleak  = (const float*)d_in[1];
    const float* vleak  = (const float*)d_in[2];
    const float* cmv    = (const float*)d_in[3];
    const float* sigma  = (const float*)d_in[4];
    const float* mu_syn = (const float*)d_in[5];
    const float* w      = (const float*)d_in[6];
    const float* erev   = (const float*)d_in[7];
    const float* s_sig  = (const float*)d_in[8];
    const float* s_mu   = (const float*)d_in[9];
    const float* s_w    = (const float*)d_in[10];
    const float* s_ev   = (const float*)d_in[11];
    const float* mu_w   = (const float*)d_in[12];
    const float* mu_b   = (const float*)d_in[13];
    const float* ls_w   = (const float*)d_in[14];
    const float* ls_b   = (const float*)d_in[15];
    float* out = (float*)d_out;

    float2 *ND0, *ND1;
    float *v1, *h1, *part;
    int* prog;
    cudaGetSymbolAddress((void**)&ND0,  g_ND0);
    cudaGetSymbolAddress((void**)&ND1,  g_ND1);
    cudaGetSymbolAddress((void**)&v1,   g_v1);
    cudaGetSymbolAddress((void**)&h1,   g_h1);
    cudaGetSymbolAddress((void**)&part, g_part);
    cudaGetSymbolAddress((void**)&prog, g_prog);

    const int SENS_SMEM = (3 * 128 * PADW + 16 * Hn) * 4;            // 210944 B
    // pipe smem words: C 16896, sensory params 26112, redND 2048,
    // senND 1024, svbuf 512, svext 512 -> 47104 words
    const int PIPE_SMEM = (128 * PADW + 3 * 128 * PADH + 2048 + 1024 + 1024) * 4;  // 188416 B
    const int GEMM_SMEM = (128 * 68 + 128 * 36) * 4;                 // 53248 B
    cudaFuncSetAttribute(sensory_kernel, cudaFuncAttributeMaxDynamicSharedMemorySize, SENS_SMEM);
    cudaFuncSetAttribute(pipe_kernel,    cudaFuncAttributeMaxDynamicSharedMemorySize, PIPE_SMEM);
    cudaFuncSetAttribute(heads_kernel,   cudaFuncAttributeMaxDynamicSharedMemorySize, GEMM_SMEM);

    init_kernel<<<1, Bn>>>(prog);
    // layer-0 sensory from x [B,T,F]: u[t][b][i] -> stride_t=F, stride_b=T*F
    sensory_kernel<<<512, 256, SENS_SMEM>>>(x, Fn, Tn * Fn,
                                            s_sig, s_mu, s_w, s_ev, ND0);
    // pipelined dual-layer recurrence (layer-1 sensory params offset by H*H)
    pipe_kernel<<<128, 512, PIPE_SMEM>>>(sigma, mu_syn, w, erev, gleak, vleak, cmv,
                                         s_sig + Hn * Hn, s_mu + Hn * Hn,
                                         s_w + Hn * Hn, s_ev + Hn * Hn,
                                         ND0, ND1, v1, h1, prog);
    // heads
    heads_kernel<<<dim3(16, 2, 32), 128, GEMM_SMEM>>>(h1, mu_w, ls_w, part);
    epilogue_kernel<<<(2 * Bn * LATn) / 256, 256>>>(part, mu_b, ls_b, out);
}